// round 3
// baseline (speedup 1.0000x reference)
#include <cuda_runtime.h>
#include <math.h>

// Problem dims (fixed by the reference)
#define BATCH   2
#define T_SEQ   2048
#define CDIM    1024
#define HEADS   16
#define DHEAD   64
#define C3      3072          // 3*C
#define MROWS   4096          // B*T

// Scratch (static __device__ arrays are the allowed scratch mechanism)
__device__ float g_qkv[(size_t)MROWS * C3];   // 48 MB
__device__ float g_y  [(size_t)MROWS * CDIM]; // 16 MB

// ---------------------------------------------------------------------------
// NT GEMM: C[M,N] = A[M,K] * B[N,K]^T   (both operands K-contiguous row-major)
// 128x128 tile, BK=16, 256 threads, 8x8 per thread.
// ---------------------------------------------------------------------------
__global__ void __launch_bounds__(256)
gemm_nt_kernel(const float* __restrict__ A,
               const float* __restrict__ B,
               float* __restrict__ C,
               int M, int N, int K)
{
    const int BM = 128, BN = 128, BK = 16;
    __shared__ __align__(16) float As[16][132];  // [k][m], +4 pad
    __shared__ __align__(16) float Bs[16][132];  // [k][n], +4 pad

    const int t  = threadIdx.x;
    const int tx = t % 16;           // n direction
    const int ty = t / 16;           // m direction
    const int m0 = blockIdx.y * BM;
    const int n0 = blockIdx.x * BN;

    float acc[8][8];
    #pragma unroll
    for (int i = 0; i < 8; i++)
        #pragma unroll
        for (int j = 0; j < 8; j++) acc[i][j] = 0.f;

    for (int k0 = 0; k0 < K; k0 += BK) {
        // Load A tile: 128 rows x 16 k = 512 float4, 2 per thread
        #pragma unroll
        for (int i = 0; i < 2; i++) {
            int idx = t + i * 256;
            int row = idx >> 2;            // 0..127
            int c4  = idx & 3;             // 0..3
            float4 v = *(const float4*)&A[(size_t)(m0 + row) * K + k0 + c4 * 4];
            As[c4*4+0][row] = v.x;
            As[c4*4+1][row] = v.y;
            As[c4*4+2][row] = v.z;
            As[c4*4+3][row] = v.w;
        }
        // Load B tile
        #pragma unroll
        for (int i = 0; i < 2; i++) {
            int idx = t + i * 256;
            int row = idx >> 2;
            int c4  = idx & 3;
            float4 v = *(const float4*)&B[(size_t)(n0 + row) * K + k0 + c4 * 4];
            Bs[c4*4+0][row] = v.x;
            Bs[c4*4+1][row] = v.y;
            Bs[c4*4+2][row] = v.z;
            Bs[c4*4+3][row] = v.w;
        }
        __syncthreads();

        #pragma unroll
        for (int kk = 0; kk < BK; kk++) {
            float a[8], b[8];
            *(float4*)&a[0] = *(const float4*)&As[kk][ty * 8];
            *(float4*)&a[4] = *(const float4*)&As[kk][ty * 8 + 4];
            *(float4*)&b[0] = *(const float4*)&Bs[kk][tx * 8];
            *(float4*)&b[4] = *(const float4*)&Bs[kk][tx * 8 + 4];
            #pragma unroll
            for (int i = 0; i < 8; i++)
                #pragma unroll
                for (int j = 0; j < 8; j++)
                    acc[i][j] += a[i] * b[j];
        }
        __syncthreads();
    }

    // Epilogue (all dims divisible by 128 — no bounds checks)
    #pragma unroll
    for (int i = 0; i < 8; i++) {
        size_t off = (size_t)(m0 + ty * 8 + i) * N + n0 + tx * 8;
        float4 v0 = make_float4(acc[i][0], acc[i][1], acc[i][2], acc[i][3]);
        float4 v1 = make_float4(acc[i][4], acc[i][5], acc[i][6], acc[i][7]);
        *(float4*)&C[off]     = v0;
        *(float4*)&C[off + 4] = v1;
    }
}

// ---------------------------------------------------------------------------
// Penalized attention, single streaming pass.
// softmax(P - Z) == softmax(P[k] + prefix_excl_sigmoid(k))  (shift-invariant).
// One warp per query row; 8 query rows per block share K/V SMEM tiles of 64
// keys. Online softmax + running sigmoid prefix. y held in registers
// (2 dims / lane).
// ---------------------------------------------------------------------------
__global__ void __launch_bounds__(256)
attn_kernel(const float* __restrict__ qkv, float* __restrict__ yout)
{
    const int b     = blockIdx.z;
    const int h     = blockIdx.y;
    const int qbase = blockIdx.x * 8;
    const int w     = threadIdx.x >> 5;
    const int lane  = threadIdx.x & 31;
    const int q     = qbase + w;

    __shared__ __align__(16) float Ksh[64][68]; // [key][d], pad->17 float4/row
    __shared__ __align__(16) float Vsh[64][68];
    __shared__ __align__(16) float qsh[8][68];
    __shared__ __align__(16) float esh[8][32];

    const float scale = 0.125f; // 1/sqrt(64)

    // Load this warp's q vector (64 floats = 16 float4)
    {
        const float* qptr = qkv + (size_t)(b * T_SEQ + q) * C3 + h * DHEAD;
        if (lane < 16)
            *(float4*)&qsh[w][lane * 4] = *(const float4*)&qptr[lane * 4];
        __syncwarp();
    }

    float m = -1e30f, denom = 0.f, run_total = 0.f;
    float y0 = 0.f, y1 = 0.f;
    const int d0 = 2 * lane;

    const int kmaxb  = qbase + 7;
    const int ntiles = (kmaxb >> 6) + 1;

    const float* Kbase = qkv + (size_t)(b * T_SEQ) * C3 + CDIM     + h * DHEAD;
    const float* Vbase = qkv + (size_t)(b * T_SEQ) * C3 + 2 * CDIM + h * DHEAD;

    for (int tile = 0; tile < ntiles; tile++) {
        const int kt0 = tile * 64;
        __syncthreads();   // previous tile's consumers done
        // Cooperative load: 64 keys x 16 float4 for K and V (coalesced rows)
        #pragma unroll
        for (int i = 0; i < 4; i++) {
            int idx = threadIdx.x + i * 256;
            int r   = idx >> 4;
            int c4  = idx & 15;
            size_t g = (size_t)(kt0 + r) * C3 + c4 * 4;
            *(float4*)&Ksh[r][c4 * 4] = *(const float4*)&Kbase[g];
            *(float4*)&Vsh[r][c4 * 4] = *(const float4*)&Vbase[g];
        }
        __syncthreads();

        // Dot products for this warp's 2 keys/lane (keys kt0+lane, kt0+32+lane)
        float p0 = 0.f, p1 = 0.f;
        {
            const float4* K0 = (const float4*)&Ksh[lane][0];
            const float4* K1 = (const float4*)&Ksh[lane + 32][0];
            const float4* Q4 = (const float4*)&qsh[w][0];
            #pragma unroll
            for (int d4 = 0; d4 < 16; d4++) {
                float4 qv = Q4[d4];
                float4 k0 = K0[d4];
                float4 k1 = K1[d4];
                p0 += qv.x * k0.x + qv.y * k0.y + qv.z * k0.z + qv.w * k0.w;
                p1 += qv.x * k1.x + qv.y * k1.y + qv.z * k1.z + qv.w * k1.w;
            }
        }

        // Two ordered 32-key chunks (scan order matters)
        #pragma unroll
        for (int half = 0; half < 2; half++) {
            const float p   = half ? p1 : p0;
            const int  key  = kt0 + half * 32 + lane;
            const bool valid = (key <= q);

            const float P = p * scale;
            float s = valid ? (1.0f / (1.0f + expf(-P))) : 0.f;

            // warp inclusive scan of s
            float sc = s;
            #pragma unroll
            for (int off = 1; off < 32; off <<= 1) {
                float tv = __shfl_up_sync(0xffffffffu, sc, off);
                if (lane >= off) sc += tv;
            }
            const float chunk_total = __shfl_sync(0xffffffffu, sc, 31);
            const float pe = run_total + sc - s;   // exclusive prefix + carry
            const float logit = valid ? (P + pe) : -1e30f;

            // online softmax update
            float cm = logit;
            #pragma unroll
            for (int off = 16; off; off >>= 1)
                cm = fmaxf(cm, __shfl_xor_sync(0xffffffffu, cm, off));
            const float m_new = fmaxf(m, cm);
            const float alpha = expf(m - m_new);
            const float e = valid ? expf(logit - m_new) : 0.f;
            float esum = e;
            #pragma unroll
            for (int off = 16; off; off >>= 1)
                esum += __shfl_xor_sync(0xffffffffu, esum, off);
            denom = denom * alpha + esum;
            m = m_new;
            run_total += chunk_total;

            // broadcast e through shared, accumulate y (2 dims / lane)
            esh[w][lane] = e;
            __syncwarp();
            y0 *= alpha; y1 *= alpha;
            const float4* E4 = (const float4*)&esh[w][0];
            const int kloc = half * 32;
            #pragma unroll
            for (int k4 = 0; k4 < 8; k4++) {
                float4 ev = E4[k4];
                float2 v0 = *(const float2*)&Vsh[kloc + k4 * 4 + 0][d0];
                float2 v1 = *(const float2*)&Vsh[kloc + k4 * 4 + 1][d0];
                float2 v2 = *(const float2*)&Vsh[kloc + k4 * 4 + 2][d0];
                float2 v3 = *(const float2*)&Vsh[kloc + k4 * 4 + 3][d0];
                y0 += ev.x * v0.x + ev.y * v1.x + ev.z * v2.x + ev.w * v3.x;
                y1 += ev.x * v0.y + ev.y * v1.y + ev.z * v2.y + ev.w * v3.y;
            }
            __syncwarp();
        }
    }

    const float inv = 1.0f / denom;
    float* yp = yout + (size_t)(b * T_SEQ + q) * CDIM + h * DHEAD + d0;
    float2 r; r.x = y0 * inv; r.y = y1 * inv;
    *(float2*)yp = r;
}

// ---------------------------------------------------------------------------
extern "C" void kernel_launch(void* const* d_in, const int* in_sizes, int n_in,
                              void* d_out, int out_size)
{
    // Identify inputs by element count (robust to metadata ordering)
    const float* x = nullptr; const float* Wa = nullptr; const float* Wp = nullptr;
    for (int i = 0; i < n_in; i++) {
        if (in_sizes[i] == BATCH * T_SEQ * CDIM)      x  = (const float*)d_in[i];
        else if (in_sizes[i] == C3 * CDIM)            Wa = (const float*)d_in[i];
        else if (in_sizes[i] == CDIM * CDIM)          Wp = (const float*)d_in[i];
    }
    float* out = (float*)d_out;

    void* qkv_p = nullptr; void* y_p = nullptr;
    cudaGetSymbolAddress(&qkv_p, g_qkv);
    cudaGetSymbolAddress(&y_p,   g_y);
    float* qkv = (float*)qkv_p;
    float* y   = (float*)y_p;

    // 1) qkv = x @ W_attn^T     [4096,1024]x[3072,1024]^T
    {
        dim3 grid(C3 / 128, MROWS / 128);
        gemm_nt_kernel<<<grid, 256>>>(x, Wa, qkv, MROWS, C3, CDIM);
    }
    // 2) penalized attention -> y [4096,1024]
    {
        dim3 grid(T_SEQ / 8, HEADS, BATCH);
        attn_kernel<<<grid, 256>>>(qkv, y);
    }
    // 3) out = y @ W_proj^T     [4096,1024]x[1024,1024]^T
    {
        dim3 grid(CDIM / 128, MROWS / 128);
        gemm_nt_kernel<<<grid, 256>>>(y, Wp, out, MROWS, CDIM, CDIM);
    }
}

// round 5
// speedup vs baseline: 1.4628x; 1.4628x over previous
#include <cuda_runtime.h>
#include <math.h>

#define BATCH   2
#define T_SEQ   2048
#define CDIM    1024
#define HEADS   16
#define DHEAD   64
#define C3      3072
#define MROWS   4096

__device__ float g_qkv[(size_t)MROWS * C3];   // 48 MB
__device__ float g_y  [(size_t)MROWS * CDIM]; // 16 MB

// ---------------------------------------------------------------------------
// NT GEMM: C[M,N] = A[M,K] * B[N,K]^T, 128x128 tile, BK=16, 256 thr, 8x8/thr.
// Double-buffered SMEM + register-staged prefetch, ONE barrier per tile.
// ---------------------------------------------------------------------------
__global__ void __launch_bounds__(256)
gemm_nt_kernel(const float* __restrict__ A,
               const float* __restrict__ B,
               float* __restrict__ C,
               int M, int N, int K)
{
    const int BK = 16;
    __shared__ __align__(16) float As[2][16][132];
    __shared__ __align__(16) float Bs[2][16][132];

    const int t  = threadIdx.x;
    const int tx = t % 16;
    const int ty = t / 16;
    const int m0 = blockIdx.y * 128;
    const int n0 = blockIdx.x * 128;

    // per-thread load coordinates (2 float4 per operand per tile)
    int lrow[2], lc4[2];
    #pragma unroll
    for (int i = 0; i < 2; i++) { int idx = t + i * 256; lrow[i] = idx >> 2; lc4[i] = idx & 3; }

    float acc[8][8];
    #pragma unroll
    for (int i = 0; i < 8; i++)
        #pragma unroll
        for (int j = 0; j < 8; j++) acc[i][j] = 0.f;

    // load tile 0 directly
    #pragma unroll
    for (int i = 0; i < 2; i++) {
        float4 va = *(const float4*)&A[(size_t)(m0 + lrow[i]) * K + lc4[i] * 4];
        float4 vb = *(const float4*)&B[(size_t)(n0 + lrow[i]) * K + lc4[i] * 4];
        As[0][lc4[i]*4+0][lrow[i]] = va.x; As[0][lc4[i]*4+1][lrow[i]] = va.y;
        As[0][lc4[i]*4+2][lrow[i]] = va.z; As[0][lc4[i]*4+3][lrow[i]] = va.w;
        Bs[0][lc4[i]*4+0][lrow[i]] = vb.x; Bs[0][lc4[i]*4+1][lrow[i]] = vb.y;
        Bs[0][lc4[i]*4+2][lrow[i]] = vb.z; Bs[0][lc4[i]*4+3][lrow[i]] = vb.w;
    }
    __syncthreads();

    const int nt = K / BK;
    for (int tt = 0; tt < nt; tt++) {
        float4 pa[2], pb[2];
        const bool has_next = (tt + 1 < nt);
        if (has_next) {
            const int kn = (tt + 1) * BK;
            #pragma unroll
            for (int i = 0; i < 2; i++) {
                pa[i] = *(const float4*)&A[(size_t)(m0 + lrow[i]) * K + kn + lc4[i] * 4];
                pb[i] = *(const float4*)&B[(size_t)(n0 + lrow[i]) * K + kn + lc4[i] * 4];
            }
        }

        const float (*Ac)[132] = As[tt & 1];
        const float (*Bc)[132] = Bs[tt & 1];
        #pragma unroll
        for (int kk = 0; kk < BK; kk++) {
            float a[8], b[8];
            *(float4*)&a[0] = *(const float4*)&Ac[kk][ty * 8];
            *(float4*)&a[4] = *(const float4*)&Ac[kk][ty * 8 + 4];
            *(float4*)&b[0] = *(const float4*)&Bc[kk][tx * 8];
            *(float4*)&b[4] = *(const float4*)&Bc[kk][tx * 8 + 4];
            #pragma unroll
            for (int i = 0; i < 8; i++)
                #pragma unroll
                for (int j = 0; j < 8; j++)
                    acc[i][j] += a[i] * b[j];
        }

        if (has_next) {
            const int nb = (tt + 1) & 1;
            #pragma unroll
            for (int i = 0; i < 2; i++) {
                As[nb][lc4[i]*4+0][lrow[i]] = pa[i].x; As[nb][lc4[i]*4+1][lrow[i]] = pa[i].y;
                As[nb][lc4[i]*4+2][lrow[i]] = pa[i].z; As[nb][lc4[i]*4+3][lrow[i]] = pa[i].w;
                Bs[nb][lc4[i]*4+0][lrow[i]] = pb[i].x; Bs[nb][lc4[i]*4+1][lrow[i]] = pb[i].y;
                Bs[nb][lc4[i]*4+2][lrow[i]] = pb[i].z; Bs[nb][lc4[i]*4+3][lrow[i]] = pb[i].w;
            }
            __syncthreads();
        }
    }

    #pragma unroll
    for (int i = 0; i < 8; i++) {
        size_t off = (size_t)(m0 + ty * 8 + i) * N + n0 + tx * 8;
        *(float4*)&C[off]     = make_float4(acc[i][0], acc[i][1], acc[i][2], acc[i][3]);
        *(float4*)&C[off + 4] = make_float4(acc[i][4], acc[i][5], acc[i][6], acc[i][7]);
    }
}

// ---------------------------------------------------------------------------
// Penalized attention, streaming pass.
// softmax(P - Z) == softmax(P[k] + prefix_excl_sigmoid(k)).
// 8 warps/block; each warp handles G=4 queries (amortizes K/V SMEM reads 4x).
// Block covers 32 queries sharing 64-key K/V tiles.
// ---------------------------------------------------------------------------
__global__ void __launch_bounds__(256)
attn_kernel(const float* __restrict__ qkv, float* __restrict__ yout)
{
    extern __shared__ float sm[];
    float (*Ksh)[68]     = (float(*)[68])sm;                          // 64x68
    float (*Vsh)[68]     = (float(*)[68])(sm + 64 * 68);              // 64x68
    float (*qsh)[68]     = (float(*)[68])(sm + 2 * 64 * 68);          // 32x68
    float (*esh)[4][64]  = (float(*)[4][64])(sm + 2 * 64 * 68 + 32 * 68); // 8x4x64

    const int b     = blockIdx.z;
    const int h     = blockIdx.y;
    const int qbase = blockIdx.x * 32;
    const int w     = threadIdx.x >> 5;
    const int lane  = threadIdx.x & 31;
    const int d0    = 2 * lane;
    const float scale = 0.125f;

    // load the block's 32 q vectors
    #pragma unroll
    for (int i = 0; i < 2; i++) {
        int idx = threadIdx.x + i * 256;
        int qr = idx >> 4, c4 = idx & 15;
        const float* qptr = qkv + (size_t)(b * T_SEQ + qbase + qr) * C3 + h * DHEAD + c4 * 4;
        *(float4*)&qsh[qr][c4 * 4] = *(const float4*)qptr;
    }

    float m[4], den[4], rtot[4], y0[4], y1[4];
    #pragma unroll
    for (int g = 0; g < 4; g++) { m[g] = -1e30f; den[g] = 0.f; rtot[g] = 0.f; y0[g] = 0.f; y1[g] = 0.f; }

    const float* Kbase = qkv + (size_t)(b * T_SEQ) * C3 + CDIM     + h * DHEAD;
    const float* Vbase = qkv + (size_t)(b * T_SEQ) * C3 + 2 * CDIM + h * DHEAD;
    const int ntiles = (qbase >> 6) + 1;

    for (int tile = 0; tile < ntiles; tile++) {
        const int kt0 = tile << 6;
        __syncthreads();  // prev-tile consumers done (also covers qsh on tile 0)
        #pragma unroll
        for (int i = 0; i < 4; i++) {
            int idx = threadIdx.x + i * 256;
            int r = idx >> 4, c4 = idx & 15;
            size_t gofs = (size_t)(kt0 + r) * C3 + c4 * 4;
            *(float4*)&Ksh[r][c4 * 4] = *(const float4*)&Kbase[gofs];
            *(float4*)&Vsh[r][c4 * 4] = *(const float4*)&Vbase[gofs];
        }
        __syncthreads();

        // --- QK: 2 keys/lane x 4 queries ---
        float p0[4] = {0.f, 0.f, 0.f, 0.f}, p1[4] = {0.f, 0.f, 0.f, 0.f};
        {
            const float4* K0 = (const float4*)&Ksh[lane][0];
            const float4* K1 = (const float4*)&Ksh[lane + 32][0];
            #pragma unroll
            for (int d4 = 0; d4 < 16; d4++) {
                float4 k0 = K0[d4], k1 = K1[d4];
                #pragma unroll
                for (int g = 0; g < 4; g++) {
                    float4 qv = *(const float4*)&qsh[w * 4 + g][d4 * 4];
                    p0[g] += qv.x * k0.x + qv.y * k0.y + qv.z * k0.z + qv.w * k0.w;
                    p1[g] += qv.x * k1.x + qv.y * k1.y + qv.z * k1.z + qv.w * k1.w;
                }
            }
        }

        // --- sigmoid prefix scan + online softmax (per query, fused 64 keys) ---
        float alpha_g[4];
        #pragma unroll
        for (int g = 0; g < 4; g++) {
            const int q = qbase + w * 4 + g;
            const int key0 = kt0 + lane;
            const bool v0 = (key0 <= q), v1 = (key0 + 32 <= q);
            const float P0 = p0[g] * scale, P1 = p1[g] * scale;
            const float s0 = v0 ? (1.0f / (1.0f + expf(-P0))) : 0.f;
            const float s1 = v1 ? (1.0f / (1.0f + expf(-P1))) : 0.f;

            float sc0 = s0, sc1 = s1;
            #pragma unroll
            for (int off = 1; off < 32; off <<= 1) {
                float t0 = __shfl_up_sync(0xffffffffu, sc0, off);
                float t1 = __shfl_up_sync(0xffffffffu, sc1, off);
                if (lane >= off) { sc0 += t0; sc1 += t1; }
            }
            const float tot0 = __shfl_sync(0xffffffffu, sc0, 31);
            const float tot1 = __shfl_sync(0xffffffffu, sc1, 31);
            const float l0 = v0 ? (P0 + rtot[g] + sc0 - s0)        : -1e30f;
            const float l1 = v1 ? (P1 + rtot[g] + tot0 + sc1 - s1) : -1e30f;
            rtot[g] += tot0 + tot1;

            float cm = fmaxf(l0, l1);
            #pragma unroll
            for (int off = 16; off; off >>= 1)
                cm = fmaxf(cm, __shfl_xor_sync(0xffffffffu, cm, off));
            const float mn = fmaxf(m[g], cm);
            const float al = __expf(m[g] - mn);
            const float e0 = v0 ? __expf(l0 - mn) : 0.f;
            const float e1 = v1 ? __expf(l1 - mn) : 0.f;
            float es = e0 + e1;
            #pragma unroll
            for (int off = 16; off; off >>= 1)
                es += __shfl_xor_sync(0xffffffffu, es, off);
            den[g] = den[g] * al + es;
            m[g] = mn;
            alpha_g[g] = al;
            esh[w][g][lane]      = e0;
            esh[w][g][lane + 32] = e1;
        }
        __syncwarp();

        // --- AV: read V tile once, feed 4 query accumulators ---
        #pragma unroll
        for (int g = 0; g < 4; g++) { y0[g] *= alpha_g[g]; y1[g] *= alpha_g[g]; }
        #pragma unroll
        for (int k4 = 0; k4 < 16; k4++) {
            float2 v0 = *(const float2*)&Vsh[k4 * 4 + 0][d0];
            float2 v1 = *(const float2*)&Vsh[k4 * 4 + 1][d0];
            float2 v2 = *(const float2*)&Vsh[k4 * 4 + 2][d0];
            float2 v3 = *(const float2*)&Vsh[k4 * 4 + 3][d0];
            #pragma unroll
            for (int g = 0; g < 4; g++) {
                float4 ev = *(const float4*)&esh[w][g][k4 * 4];
                y0[g] += ev.x * v0.x + ev.y * v1.x + ev.z * v2.x + ev.w * v3.x;
                y1[g] += ev.x * v0.y + ev.y * v1.y + ev.z * v2.y + ev.w * v3.y;
            }
        }
        __syncwarp();
    }

    #pragma unroll
    for (int g = 0; g < 4; g++) {
        const int q = qbase + w * 4 + g;
        const float inv = 1.0f / den[g];
        float* yp = yout + (size_t)(b * T_SEQ + q) * CDIM + h * DHEAD + d0;
        float2 r; r.x = y0[g] * inv; r.y = y1[g] * inv;
        *(float2*)yp = r;
    }
}

// ---------------------------------------------------------------------------
extern "C" void kernel_launch(void* const* d_in, const int* in_sizes, int n_in,
                              void* d_out, int out_size)
{
    const float* x = nullptr; const float* Wa = nullptr; const float* Wp = nullptr;
    for (int i = 0; i < n_in; i++) {
        if (in_sizes[i] == BATCH * T_SEQ * CDIM)  x  = (const float*)d_in[i];
        else if (in_sizes[i] == C3 * CDIM)        Wa = (const float*)d_in[i];
        else if (in_sizes[i] == CDIM * CDIM)      Wp = (const float*)d_in[i];
    }
    float* out = (float*)d_out;

    void* qkv_p = nullptr; void* y_p = nullptr;
    cudaGetSymbolAddress(&qkv_p, g_qkv);
    cudaGetSymbolAddress(&y_p,   g_y);
    float* qkv = (float*)qkv_p;
    float* y   = (float*)y_p;

    const int ATTN_SMEM = (2 * 64 * 68 + 32 * 68 + 8 * 4 * 64) * 4;  // 51712 B
    cudaFuncSetAttribute(attn_kernel, cudaFuncAttributeMaxDynamicSharedMemorySize, ATTN_SMEM);

    {   // qkv = x @ W_attn^T
        dim3 grid(C3 / 128, MROWS / 128);
        gemm_nt_kernel<<<grid, 256>>>(x, Wa, qkv, MROWS, C3, CDIM);
    }
    {   // penalized attention
        dim3 grid(T_SEQ / 32, HEADS, BATCH);
        attn_kernel<<<grid, 256, ATTN_SMEM>>>(qkv, y);
    }
    {   // out = y @ W_proj^T
        dim3 grid(CDIM / 128, MROWS / 128);
        gemm_nt_kernel<<<grid, 256>>>(y, Wp, out, MROWS, CDIM, CDIM);
    }
}